// round 8
// baseline (speedup 1.0000x reference)
#include <cuda_runtime.h>
#include <cstdint>

#define B_  8
#define S_  4096
#define H_  768
#define D_  64
#define BQ  128
#define BK  64
#define SSTR 68   // smem row stride; 68 % 32 == 4 -> conflict-free frag loads

// scratch
__device__ float g_q [B_ * S_ * D_];        // [b*S + s][d]
__device__ float g_k [B_ * S_ * D_];        // [b*S + s][d]
__device__ float g_vt[B_ * D_ * S_];        // transposed: [b][d][s]
__device__ float g_wt[3][D_ * H_];          // W^T: [n][k]

// split-K partial buffers: index pi = (b*32+qt)*3 + chunk
__device__ float g_po[8 * 32 * 3 * 128 * 64];   // unnormalized O
__device__ float g_pm[8 * 32 * 3 * 128];        // row max
__device__ float g_pl[8 * 32 * 3 * 128];        // row sum

#define NCHUNK(qt) ((qt) < 12 ? 1 : ((qt) < 24 ? 2 : 3))

__device__ __forceinline__ unsigned f2tf(float f) {
    unsigned u; asm("cvt.rna.tf32.f32 %0, %1;" : "=r"(u) : "f"(f)); return u;
}
__device__ __forceinline__ float tf(float f) { return __uint_as_float(f2tf(f)); }

__device__ __forceinline__ void mma8(float* c, unsigned a0, unsigned a1, unsigned a2, unsigned a3,
                                     unsigned b0, unsigned b1) {
    asm("mma.sync.aligned.m16n8k8.row.col.f32.tf32.tf32.f32 "
        "{%0,%1,%2,%3}, {%4,%5,%6,%7}, {%8,%9}, {%0,%1,%2,%3};"
        : "+f"(c[0]), "+f"(c[1]), "+f"(c[2]), "+f"(c[3])
        : "r"(a0), "r"(a1), "r"(a2), "r"(a3), "r"(b0), "r"(b1));
}

// ---------------------------------------------------------------------------
// Kernel 0: transpose W into g_wt
// ---------------------------------------------------------------------------
__global__ void wt_kernel(const float* __restrict__ Wq,
                          const float* __restrict__ Wk,
                          const float* __restrict__ Wv) {
    int idx = blockIdx.x * blockDim.x + threadIdx.x;
    if (idx >= D_ * H_) return;
    int n = idx / H_, k = idx % H_;
    g_wt[0][idx] = Wq[k * D_ + n];
    g_wt[1][idx] = Wk[k * D_ + n];
    g_wt[2][idx] = Wv[k * D_ + n];
}

// ---------------------------------------------------------------------------
// Kernel 1: QKV projection, tf32 mma.sync, double-buffered smem ping-pong.
// One __syncthreads per 64-wide K-chunk (load next buffer while mma on cur).
// ---------------------------------------------------------------------------
#define QKV_SMEM (2 * (BQ + 64) * SSTR * (int)sizeof(float))

__global__ void __launch_bounds__(256, 2) qkv_kernel(
    const float* __restrict__ x,
    const float* __restrict__ bq, const float* __restrict__ bk, const float* __restrict__ bv)
{
    extern __shared__ float sm[];
    float* xsb[2] = { sm,                sm + 192 * SSTR };
    float* wsb[2] = { sm + BQ * SSTR,    sm + 320 * SSTR };

    const int p = blockIdx.y;
    const float* wt   = g_wt[p];
    const float* bias = (p == 0) ? bq : ((p == 1) ? bk : bv);

    const int tid = threadIdx.x;
    const int w = tid >> 5, lane = tid & 31, g = lane >> 2, t = lane & 3;
    const int row0 = blockIdx.x * BQ;

    float acc[8][4] = {};

    // chunk loader: LDG (f32) -> cvt tf32 -> STS into buffer buf
    auto load_chunk = [&](int buf, int k0) {
        float* xs = xsb[buf];
        float* ws = wsb[buf];
        #pragma unroll
        for (int i = 0; i < 8; i++) {
            int e = tid + i * 256;
            int r = e >> 4, c4 = (e & 15) * 4;
            float4 v = *(const float4*)&x[(size_t)(row0 + r) * H_ + k0 + c4];
            float* d = &xs[r * SSTR + c4];
            d[0] = tf(v.x); d[1] = tf(v.y); d[2] = tf(v.z); d[3] = tf(v.w);
        }
        #pragma unroll
        for (int i = 0; i < 4; i++) {
            int e = tid + i * 256;
            int r = e >> 4, c4 = (e & 15) * 4;
            float4 v = *(const float4*)&wt[(size_t)r * H_ + k0 + c4];
            float* d = &ws[r * SSTR + c4];
            d[0] = tf(v.x); d[1] = tf(v.y); d[2] = tf(v.z); d[3] = tf(v.w);
        }
    };

    load_chunk(0, 0);
    __syncthreads();

    for (int ch = 0; ch < 12; ch++) {
        const int cur = ch & 1;
        if (ch < 11) load_chunk(1 - cur, (ch + 1) * 64);   // fill other buffer

        const float* xs = xsb[cur];
        const float* ws = wsb[cur];
        #pragma unroll
        for (int s = 0; s < 8; s++) {
            const float* ap = &xs[(16 * w + g) * SSTR + 8 * s + t];
            unsigned a0 = __float_as_uint(ap[0]);
            unsigned a1 = __float_as_uint(ap[8 * SSTR]);
            unsigned a2 = __float_as_uint(ap[4]);
            unsigned a3 = __float_as_uint(ap[8 * SSTR + 4]);
            #pragma unroll
            for (int j = 0; j < 8; j++) {
                unsigned b0 = __float_as_uint(ws[(8 * j + g) * SSTR + 8 * s + t]);
                unsigned b1 = __float_as_uint(ws[(8 * j + g) * SSTR + 8 * s + t + 4]);
                mma8(acc[j], a0, a1, a2, a3, b0, b1);
            }
        }
        __syncthreads();   // next-buffer writes done block-wide; cur reads done
    }

    const int r_g = row0 + 16 * w + g;
    if (p < 2) {
        float* out = (p == 0) ? g_q : g_k;
        #pragma unroll
        for (int j = 0; j < 8; j++) {
            int c = 8 * j + 2 * t;
            float b0v = __ldg(&bias[c]), b1v = __ldg(&bias[c + 1]);
            *(float2*)&out[(size_t)r_g * D_ + c]       = make_float2(acc[j][0] + b0v, acc[j][1] + b1v);
            *(float2*)&out[(size_t)(r_g + 8) * D_ + c] = make_float2(acc[j][2] + b0v, acc[j][3] + b1v);
        }
    } else {
        int b = r_g >> 12, s0 = r_g & (S_ - 1);
        float* out = g_vt + (size_t)b * D_ * S_;
        #pragma unroll
        for (int j = 0; j < 8; j++) {
            int c = 8 * j + 2 * t;
            float b0v = __ldg(&bias[c]), b1v = __ldg(&bias[c + 1]);
            out[(size_t)c * S_ + s0]           = acc[j][0] + b0v;
            out[(size_t)(c + 1) * S_ + s0]     = acc[j][1] + b1v;
            out[(size_t)c * S_ + s0 + 8]       = acc[j][2] + b0v;
            out[(size_t)(c + 1) * S_ + s0 + 8] = acc[j][3] + b1v;
        }
    }
}

// ---------------------------------------------------------------------------
// Kernel 2: split-K causal flash attention chunk (K-tile register prefetch).
// ---------------------------------------------------------------------------
#define ASMEM ((BQ + BK + BK + BQ) * SSTR * (int)sizeof(float))

__global__ void __launch_bounds__(256, 2) attn_chunk_kernel(float* __restrict__ out)
{
    extern __shared__ float sm[];
    float* Qs  = sm;
    float* Ks  = Qs  + BQ * SSTR;
    float* Vts = Ks  + BK * SSTR;
    float* Ps  = Vts + BK * SSTR;

    // decode work item (LPT order: heaviest first)
    const int b  = blockIdx.x & 7;
    const int w_ = blockIdx.x >> 3;        // 0..59
    int qt, chunk;
    if (w_ < 24)      { qt = 23 - (w_ >> 1);        chunk = w_ & 1; }
    else if (w_ < 48) { int u = w_ - 24; qt = 24 + u / 3; chunk = u % 3; }
    else              { qt = 59 - w_;               chunk = 0; }
    const int nkt = 2 * qt + 2;
    const int nc  = NCHUNK(qt);
    const int base = nkt / nc, rem = nkt % nc;
    const int k0  = chunk * base + (chunk < rem ? chunk : rem);
    const int k1  = k0 + base + (chunk < rem ? 1 : 0);

    const int tid = threadIdx.x;
    const int w = tid >> 5, lane = tid & 31, g = lane >> 2, t = lane & 3;

    const float* q  = g_q  + (size_t)b * S_ * D_;
    const float* kp = g_k  + (size_t)b * S_ * D_;
    const float* vt = g_vt + (size_t)b * D_ * S_;

    #pragma unroll
    for (int i = 0; i < 8; i++) {                 // Q tile
        int e = tid + i * 256;
        int r = e >> 4, c4 = (e & 15) * 4;
        float4 v = *(const float4*)&q[(size_t)(qt * BQ + r) * D_ + c4];
        float* d = &Qs[r * SSTR + c4];
        d[0] = tf(v.x); d[1] = tf(v.y); d[2] = tf(v.z); d[3] = tf(v.w);
    }

    float4 kreg[4];
    auto ldg_k = [&](int kt) {
        #pragma unroll
        for (int i = 0; i < 4; i++) {
            int e = tid + i * 256;
            int r = e >> 4, c4 = (e & 15) * 4;
            kreg[i] = *(const float4*)&kp[(size_t)(kt * BK + r) * D_ + c4];
        }
    };
    ldg_k(k0);

    float o[8][4] = {};
    float m0 = -1e30f, m1 = -1e30f, l0 = 0.f, l1 = 0.f;
    const float scale = 0.125f;

    for (int kt = k0; kt < k1; kt++) {
        __syncthreads();                          // prev tile's reads done
        #pragma unroll
        for (int i = 0; i < 4; i++) {             // STS prefetched K tile
            int e = tid + i * 256;
            int r = e >> 4, c4 = (e & 15) * 4;
            float* d = &Ks[r * SSTR + c4];
            d[0] = tf(kreg[i].x); d[1] = tf(kreg[i].y);
            d[2] = tf(kreg[i].z); d[3] = tf(kreg[i].w);
        }
        #pragma unroll
        for (int i = 0; i < 4; i++) {             // V^T tile
            int e = tid + i * 256;
            int r = e >> 4, c4 = (e & 15) * 4;
            float4 v = *(const float4*)&vt[(size_t)r * S_ + kt * BK + c4];
            float* d = &Vts[r * SSTR + c4];
            d[0] = tf(v.x); d[1] = tf(v.y); d[2] = tf(v.z); d[3] = tf(v.w);
        }
        if (kt + 1 < k1) ldg_k(kt + 1);           // prefetch next K (hidden under compute)
        __syncthreads();

        float sc[8][4] = {};
        #pragma unroll
        for (int s = 0; s < 8; s++) {
            const float* ap = &Qs[(16 * w + g) * SSTR + 8 * s + t];
            unsigned a0 = __float_as_uint(ap[0]);
            unsigned a1 = __float_as_uint(ap[8 * SSTR]);
            unsigned a2 = __float_as_uint(ap[4]);
            unsigned a3 = __float_as_uint(ap[8 * SSTR + 4]);
            #pragma unroll
            for (int j = 0; j < 8; j++) {
                unsigned b0 = __float_as_uint(Ks[(8 * j + g) * SSTR + 8 * s + t]);
                unsigned b1 = __float_as_uint(Ks[(8 * j + g) * SSTR + 8 * s + t + 4]);
                mma8(sc[j], a0, a1, a2, a3, b0, b1);
            }
        }

        #pragma unroll
        for (int j = 0; j < 8; j++) {
            sc[j][0] *= scale; sc[j][1] *= scale; sc[j][2] *= scale; sc[j][3] *= scale;
        }
        if (kt >= nkt - 2) {                      // diagonal masking (global kt)
            const int row_g = qt * BQ + 16 * w + g;
            #pragma unroll
            for (int j = 0; j < 8; j++) {
                int key = kt * BK + 8 * j + 2 * t;
                if (key     > row_g)     sc[j][0] = -1e30f;
                if (key + 1 > row_g)     sc[j][1] = -1e30f;
                if (key     > row_g + 8) sc[j][2] = -1e30f;
                if (key + 1 > row_g + 8) sc[j][3] = -1e30f;
            }
        }

        float mt0 = -1e30f, mt1 = -1e30f;
        #pragma unroll
        for (int j = 0; j < 8; j++) {
            mt0 = fmaxf(mt0, fmaxf(sc[j][0], sc[j][1]));
            mt1 = fmaxf(mt1, fmaxf(sc[j][2], sc[j][3]));
        }
        mt0 = fmaxf(mt0, __shfl_xor_sync(~0u, mt0, 1));
        mt0 = fmaxf(mt0, __shfl_xor_sync(~0u, mt0, 2));
        mt1 = fmaxf(mt1, __shfl_xor_sync(~0u, mt1, 1));
        mt1 = fmaxf(mt1, __shfl_xor_sync(~0u, mt1, 2));
        float mn0 = fmaxf(m0, mt0), mn1 = fmaxf(m1, mt1);
        float c0 = __expf(m0 - mn0), c1 = __expf(m1 - mn1);
        m0 = mn0; m1 = mn1;

        float rs0 = 0.f, rs1 = 0.f;
        float* prow0 = &Ps[(16 * w + g) * SSTR];
        float* prow1 = prow0 + 8 * SSTR;
        #pragma unroll
        for (int j = 0; j < 8; j++) {
            float e0 = __expf(sc[j][0] - mn0), e1 = __expf(sc[j][1] - mn0);
            float e2 = __expf(sc[j][2] - mn1), e3 = __expf(sc[j][3] - mn1);
            rs0 += e0 + e1; rs1 += e2 + e3;
            int c = 8 * j + 2 * t;
            *(float2*)&prow0[c] = make_float2(tf(e0), tf(e1));
            *(float2*)&prow1[c] = make_float2(tf(e2), tf(e3));
        }
        rs0 += __shfl_xor_sync(~0u, rs0, 1); rs0 += __shfl_xor_sync(~0u, rs0, 2);
        rs1 += __shfl_xor_sync(~0u, rs1, 1); rs1 += __shfl_xor_sync(~0u, rs1, 2);
        l0 = l0 * c0 + rs0; l1 = l1 * c1 + rs1;
        #pragma unroll
        for (int j = 0; j < 8; j++) {
            o[j][0] *= c0; o[j][1] *= c0; o[j][2] *= c1; o[j][3] *= c1;
        }
        __syncwarp();

        #pragma unroll
        for (int s = 0; s < 8; s++) {
            const float* ap = &Ps[(16 * w + g) * SSTR + 8 * s + t];
            unsigned a0 = __float_as_uint(ap[0]);
            unsigned a1 = __float_as_uint(ap[8 * SSTR]);
            unsigned a2 = __float_as_uint(ap[4]);
            unsigned a3 = __float_as_uint(ap[8 * SSTR + 4]);
            #pragma unroll
            for (int j = 0; j < 8; j++) {
                unsigned b0 = __float_as_uint(Vts[(8 * j + g) * SSTR + 8 * s + t]);
                unsigned b1 = __float_as_uint(Vts[(8 * j + g) * SSTR + 8 * s + t + 4]);
                mma8(o[j], a0, a1, a2, a3, b0, b1);
            }
        }
    }

    const int rl0 = 16 * w + g;                   // local rows rl0, rl0+8
    if (nc == 1) {
        float i0 = 1.f / l0, i1 = 1.f / l1;
        float* op = out + ((size_t)b * S_ + qt * BQ + rl0) * D_;
        #pragma unroll
        for (int j = 0; j < 8; j++) {
            int c = 8 * j + 2 * t;
            *(float2*)&op[c]          = make_float2(o[j][0] * i0, o[j][1] * i0);
            *(float2*)&op[8 * D_ + c] = make_float2(o[j][2] * i1, o[j][3] * i1);
        }
    } else {
        const int pi = (b * 32 + qt) * 3 + chunk;
        float* po = g_po + (size_t)pi * 128 * 64;
        #pragma unroll
        for (int j = 0; j < 8; j++) {
            int c = 8 * j + 2 * t;
            *(float2*)&po[rl0 * 64 + c]       = make_float2(o[j][0], o[j][1]);
            *(float2*)&po[(rl0 + 8) * 64 + c] = make_float2(o[j][2], o[j][3]);
        }
        if (t == 0) {
            g_pm[pi * 128 + rl0]     = m0;
            g_pm[pi * 128 + rl0 + 8] = m1;
            g_pl[pi * 128 + rl0]     = l0;
            g_pl[pi * 128 + rl0 + 8] = l1;
        }
    }
}

// ---------------------------------------------------------------------------
// Kernel 3: merge split-K partials for qt >= 12.  grid=(80,8), block=256.
// 4 CTAs per (b,qt); float4 vectorized.
// ---------------------------------------------------------------------------
__global__ void __launch_bounds__(256) merge_kernel(float* __restrict__ out)
{
    const int qt  = 12 + (blockIdx.x >> 2);
    const int sub = blockIdx.x & 3;
    const int b   = blockIdx.y;
    const int nc  = NCHUNK(qt);
    const int pib = (b * 32 + qt) * 3;

    #pragma unroll
    for (int it = 0; it < 2; it++) {
        const int e4 = sub * 512 + it * 256 + threadIdx.x;   // float4 index in [0,2048)
        const int e  = e4 * 4;
        const int r  = e >> 6, col = e & 63;

        float M = -1e30f;
        #pragma unroll
        for (int c = 0; c < 3; c++)
            if (c < nc) M = fmaxf(M, g_pm[(pib + c) * 128 + r]);
        float L = 0.f;
        float4 O = make_float4(0.f, 0.f, 0.f, 0.f);
        #pragma unroll
        for (int c = 0; c < 3; c++)
            if (c < nc) {
                float wgt = __expf(g_pm[(pib + c) * 128 + r] - M);
                L += g_pl[(pib + c) * 128 + r] * wgt;
                float4 v = *(const float4*)&g_po[(size_t)(pib + c) * 8192 + e];
                O.x += v.x * wgt; O.y += v.y * wgt; O.z += v.z * wgt; O.w += v.w * wgt;
            }
        float inv = 1.f / L;
        O.x *= inv; O.y *= inv; O.z *= inv; O.w *= inv;
        *(float4*)&out[((size_t)b * S_ + qt * BQ + r) * D_ + col] = O;
    }
}

// ---------------------------------------------------------------------------
extern "C" void kernel_launch(void* const* d_in, const int* in_sizes, int n_in,
                              void* d_out, int out_size)
{
    const float* x  = (const float*)d_in[0];
    const float* Wq = (const float*)d_in[1];
    const float* bq = (const float*)d_in[2];
    const float* Wk = (const float*)d_in[3];
    const float* bk = (const float*)d_in[4];
    const float* Wv = (const float*)d_in[5];
    const float* bv = (const float*)d_in[6];
    float* out = (float*)d_out;

    cudaFuncSetAttribute(qkv_kernel,        cudaFuncAttributeMaxDynamicSharedMemorySize, QKV_SMEM);
    cudaFuncSetAttribute(attn_chunk_kernel, cudaFuncAttributeMaxDynamicSharedMemorySize, ASMEM);

    wt_kernel<<<(D_ * H_ + 255) / 256, 256>>>(Wq, Wk, Wv);

    dim3 g1((B_ * S_) / BQ, 3);
    qkv_kernel<<<g1, 256, QKV_SMEM>>>(x, bq, bk, bv);

    attn_chunk_kernel<<<480, 256, ASMEM>>>(out);

    dim3 g3(80, 8);
    merge_kernel<<<g3, 256>>>(out);
}

// round 10
// speedup vs baseline: 1.2592x; 1.2592x over previous
#include <cuda_runtime.h>
#include <cstdint>

#define B_  8
#define S_  4096
#define H_  768
#define D_  64
#define BQ  128
#define BK  64
#define SSTR 68   // smem row stride; 68 % 32 == 4 -> conflict-free frag loads

// scratch
__device__ float g_q [B_ * S_ * D_];        // [b*S + s][d]
__device__ float g_k [B_ * S_ * D_];        // [b*S + s][d]
__device__ float g_vt[B_ * D_ * S_];        // transposed: [b][d][s]
__device__ float g_wt[3][D_ * H_];          // W^T: [n][k]

// split-K partial buffers: index pi = (b*32+qt)*3 + chunk
__device__ float g_po[8 * 32 * 3 * 128 * 64];   // unnormalized O
__device__ float g_pm[8 * 32 * 3 * 128];        // row max
__device__ float g_pl[8 * 32 * 3 * 128];        // row sum

#define NCHUNK(qt) ((qt) < 12 ? 1 : ((qt) < 24 ? 2 : 3))

__device__ __forceinline__ unsigned f2tf(float f) {
    unsigned u; asm("cvt.rna.tf32.f32 %0, %1;" : "=r"(u) : "f"(f)); return u;
}
__device__ __forceinline__ float tf(float f) { return __uint_as_float(f2tf(f)); }

__device__ __forceinline__ void mma8(float* c, unsigned a0, unsigned a1, unsigned a2, unsigned a3,
                                     unsigned b0, unsigned b1) {
    asm("mma.sync.aligned.m16n8k8.row.col.f32.tf32.tf32.f32 "
        "{%0,%1,%2,%3}, {%4,%5,%6,%7}, {%8,%9}, {%0,%1,%2,%3};"
        : "+f"(c[0]), "+f"(c[1]), "+f"(c[2]), "+f"(c[3])
        : "r"(a0), "r"(a1), "r"(a2), "r"(a3), "r"(b0), "r"(b1));
}

// ---------------------------------------------------------------------------
// Kernel 0: transpose W into g_wt
// ---------------------------------------------------------------------------
__global__ void wt_kernel(const float* __restrict__ Wq,
                          const float* __restrict__ Wk,
                          const float* __restrict__ Wv) {
    int idx = blockIdx.x * blockDim.x + threadIdx.x;
    if (idx >= D_ * H_) return;
    int n = idx / H_, k = idx % H_;
    g_wt[0][idx] = Wq[k * D_ + n];
    g_wt[1][idx] = Wk[k * D_ + n];
    g_wt[2][idx] = Wv[k * D_ + n];
}

// ---------------------------------------------------------------------------
// Kernel 1: QKV projection, tf32 mma.sync (proven R5 version).
// ---------------------------------------------------------------------------
#define QKV_SMEM ((BQ + 64) * SSTR * (int)sizeof(float))

__global__ void __launch_bounds__(256, 2) qkv_kernel(
    const float* __restrict__ x,
    const float* __restrict__ bq, const float* __restrict__ bk, const float* __restrict__ bv)
{
    extern __shared__ float sm[];
    float* xs = sm;                 // [128][SSTR]
    float* ws = sm + BQ * SSTR;     // [64][SSTR]

    const int p = blockIdx.y;
    const float* wt   = g_wt[p];
    const float* bias = (p == 0) ? bq : ((p == 1) ? bk : bv);

    const int tid = threadIdx.x;
    const int w = tid >> 5, lane = tid & 31, g = lane >> 2, t = lane & 3;
    const int row0 = blockIdx.x * BQ;

    float acc[8][4] = {};

    for (int k0 = 0; k0 < H_; k0 += 64) {
        __syncthreads();
        #pragma unroll
        for (int i = 0; i < 8; i++) {
            int e = tid + i * 256;
            int r = e >> 4, c4 = (e & 15) * 4;
            float4 v = *(const float4*)&x[(size_t)(row0 + r) * H_ + k0 + c4];
            float* d = &xs[r * SSTR + c4];
            d[0] = tf(v.x); d[1] = tf(v.y); d[2] = tf(v.z); d[3] = tf(v.w);
        }
        #pragma unroll
        for (int i = 0; i < 4; i++) {
            int e = tid + i * 256;
            int r = e >> 4, c4 = (e & 15) * 4;
            float4 v = *(const float4*)&wt[(size_t)r * H_ + k0 + c4];
            float* d = &ws[r * SSTR + c4];
            d[0] = tf(v.x); d[1] = tf(v.y); d[2] = tf(v.z); d[3] = tf(v.w);
        }
        __syncthreads();

        #pragma unroll
        for (int s = 0; s < 8; s++) {
            const float* ap = &xs[(16 * w + g) * SSTR + 8 * s + t];
            unsigned a0 = __float_as_uint(ap[0]);
            unsigned a1 = __float_as_uint(ap[8 * SSTR]);
            unsigned a2 = __float_as_uint(ap[4]);
            unsigned a3 = __float_as_uint(ap[8 * SSTR + 4]);
            #pragma unroll
            for (int j = 0; j < 8; j++) {
                unsigned b0 = __float_as_uint(ws[(8 * j + g) * SSTR + 8 * s + t]);
                unsigned b1 = __float_as_uint(ws[(8 * j + g) * SSTR + 8 * s + t + 4]);
                mma8(acc[j], a0, a1, a2, a3, b0, b1);
            }
        }
    }

    const int r_g = row0 + 16 * w + g;
    if (p < 2) {
        float* out = (p == 0) ? g_q : g_k;
        #pragma unroll
        for (int j = 0; j < 8; j++) {
            int c = 8 * j + 2 * t;
            float b0v = __ldg(&bias[c]), b1v = __ldg(&bias[c + 1]);
            *(float2*)&out[(size_t)r_g * D_ + c]       = make_float2(acc[j][0] + b0v, acc[j][1] + b1v);
            *(float2*)&out[(size_t)(r_g + 8) * D_ + c] = make_float2(acc[j][2] + b0v, acc[j][3] + b1v);
        }
    } else {
        int b = r_g >> 12, s0 = r_g & (S_ - 1);
        float* out = g_vt + (size_t)b * D_ * S_;
        #pragma unroll
        for (int j = 0; j < 8; j++) {
            int c = 8 * j + 2 * t;
            float b0v = __ldg(&bias[c]), b1v = __ldg(&bias[c + 1]);
            out[(size_t)c * S_ + s0]           = acc[j][0] + b0v;
            out[(size_t)(c + 1) * S_ + s0]     = acc[j][1] + b1v;
            out[(size_t)c * S_ + s0 + 8]       = acc[j][2] + b0v;
            out[(size_t)(c + 1) * S_ + s0 + 8] = acc[j][3] + b1v;
        }
    }
}

// ---------------------------------------------------------------------------
// Kernel 2: split-K causal flash attention chunk (proven R5 version).
// 480 CTAs = 60 work items x 8 batches, launched heaviest-first (LPT).
// ---------------------------------------------------------------------------
#define ASMEM ((BQ + BK + BK + BQ) * SSTR * (int)sizeof(float))

__global__ void __launch_bounds__(256, 2) attn_chunk_kernel(float* __restrict__ out)
{
    extern __shared__ float sm[];
    float* Qs  = sm;
    float* Ks  = Qs  + BQ * SSTR;
    float* Vts = Ks  + BK * SSTR;
    float* Ps  = Vts + BK * SSTR;

    // decode work item
    const int b  = blockIdx.x & 7;
    const int w_ = blockIdx.x >> 3;        // 0..59
    int qt, chunk;
    if (w_ < 24)      { qt = 23 - (w_ >> 1);        chunk = w_ & 1; }
    else if (w_ < 48) { int u = w_ - 24; qt = 24 + u / 3; chunk = u % 3; }
    else              { qt = 59 - w_;               chunk = 0; }
    const int nkt = 2 * qt + 2;
    const int nc  = NCHUNK(qt);
    const int base = nkt / nc, rem = nkt % nc;
    const int k0  = chunk * base + (chunk < rem ? chunk : rem);
    const int k1  = k0 + base + (chunk < rem ? 1 : 0);

    const int tid = threadIdx.x;
    const int w = tid >> 5, lane = tid & 31, g = lane >> 2, t = lane & 3;

    const float* q  = g_q  + (size_t)b * S_ * D_;
    const float* kp = g_k  + (size_t)b * S_ * D_;
    const float* vt = g_vt + (size_t)b * D_ * S_;

    #pragma unroll
    for (int i = 0; i < 8; i++) {                 // Q tile
        int e = tid + i * 256;
        int r = e >> 4, c4 = (e & 15) * 4;
        float4 v = *(const float4*)&q[(size_t)(qt * BQ + r) * D_ + c4];
        float* d = &Qs[r * SSTR + c4];
        d[0] = tf(v.x); d[1] = tf(v.y); d[2] = tf(v.z); d[3] = tf(v.w);
    }

    float o[8][4] = {};
    float m0 = -1e30f, m1 = -1e30f, l0 = 0.f, l1 = 0.f;
    const float scale = 0.125f;

    for (int kt = k0; kt < k1; kt++) {
        __syncthreads();
        #pragma unroll
        for (int i = 0; i < 4; i++) {
            int e = tid + i * 256;
            int r = e >> 4, c4 = (e & 15) * 4;
            float4 v = *(const float4*)&kp[(size_t)(kt * BK + r) * D_ + c4];
            float* d = &Ks[r * SSTR + c4];
            d[0] = tf(v.x); d[1] = tf(v.y); d[2] = tf(v.z); d[3] = tf(v.w);
        }
        #pragma unroll
        for (int i = 0; i < 4; i++) {
            int e = tid + i * 256;
            int r = e >> 4, c4 = (e & 15) * 4;
            float4 v = *(const float4*)&vt[(size_t)r * S_ + kt * BK + c4];
            float* d = &Vts[r * SSTR + c4];
            d[0] = tf(v.x); d[1] = tf(v.y); d[2] = tf(v.z); d[3] = tf(v.w);
        }
        __syncthreads();

        float sc[8][4] = {};
        #pragma unroll
        for (int s = 0; s < 8; s++) {
            const float* ap = &Qs[(16 * w + g) * SSTR + 8 * s + t];
            unsigned a0 = __float_as_uint(ap[0]);
            unsigned a1 = __float_as_uint(ap[8 * SSTR]);
            unsigned a2 = __float_as_uint(ap[4]);
            unsigned a3 = __float_as_uint(ap[8 * SSTR + 4]);
            #pragma unroll
            for (int j = 0; j < 8; j++) {
                unsigned b0 = __float_as_uint(Ks[(8 * j + g) * SSTR + 8 * s + t]);
                unsigned b1 = __float_as_uint(Ks[(8 * j + g) * SSTR + 8 * s + t + 4]);
                mma8(sc[j], a0, a1, a2, a3, b0, b1);
            }
        }

        #pragma unroll
        for (int j = 0; j < 8; j++) {
            sc[j][0] *= scale; sc[j][1] *= scale; sc[j][2] *= scale; sc[j][3] *= scale;
        }
        if (kt >= nkt - 2) {                      // diagonal masking (global kt)
            const int row_g = qt * BQ + 16 * w + g;
            #pragma unroll
            for (int j = 0; j < 8; j++) {
                int key = kt * BK + 8 * j + 2 * t;
                if (key     > row_g)     sc[j][0] = -1e30f;
                if (key + 1 > row_g)     sc[j][1] = -1e30f;
                if (key     > row_g + 8) sc[j][2] = -1e30f;
                if (key + 1 > row_g + 8) sc[j][3] = -1e30f;
            }
        }

        float mt0 = -1e30f, mt1 = -1e30f;
        #pragma unroll
        for (int j = 0; j < 8; j++) {
            mt0 = fmaxf(mt0, fmaxf(sc[j][0], sc[j][1]));
            mt1 = fmaxf(mt1, fmaxf(sc[j][2], sc[j][3]));
        }
        mt0 = fmaxf(mt0, __shfl_xor_sync(~0u, mt0, 1));
        mt0 = fmaxf(mt0, __shfl_xor_sync(~0u, mt0, 2));
        mt1 = fmaxf(mt1, __shfl_xor_sync(~0u, mt1, 1));
        mt1 = fmaxf(mt1, __shfl_xor_sync(~0u, mt1, 2));
        float mn0 = fmaxf(m0, mt0), mn1 = fmaxf(m1, mt1);
        float c0 = __expf(m0 - mn0), c1 = __expf(m1 - mn1);
        m0 = mn0; m1 = mn1;

        float rs0 = 0.f, rs1 = 0.f;
        float* prow0 = &Ps[(16 * w + g) * SSTR];
        float* prow1 = prow0 + 8 * SSTR;
        #pragma unroll
        for (int j = 0; j < 8; j++) {
            float e0 = __expf(sc[j][0] - mn0), e1 = __expf(sc[j][1] - mn0);
            float e2 = __expf(sc[j][2] - mn1), e3 = __expf(sc[j][3] - mn1);
            rs0 += e0 + e1; rs1 += e2 + e3;
            int c = 8 * j + 2 * t;
            *(float2*)&prow0[c] = make_float2(tf(e0), tf(e1));
            *(float2*)&prow1[c] = make_float2(tf(e2), tf(e3));
        }
        rs0 += __shfl_xor_sync(~0u, rs0, 1); rs0 += __shfl_xor_sync(~0u, rs0, 2);
        rs1 += __shfl_xor_sync(~0u, rs1, 1); rs1 += __shfl_xor_sync(~0u, rs1, 2);
        l0 = l0 * c0 + rs0; l1 = l1 * c1 + rs1;
        #pragma unroll
        for (int j = 0; j < 8; j++) {
            o[j][0] *= c0; o[j][1] *= c0; o[j][2] *= c1; o[j][3] *= c1;
        }
        __syncwarp();

        #pragma unroll
        for (int s = 0; s < 8; s++) {
            const float* ap = &Ps[(16 * w + g) * SSTR + 8 * s + t];
            unsigned a0 = __float_as_uint(ap[0]);
            unsigned a1 = __float_as_uint(ap[8 * SSTR]);
            unsigned a2 = __float_as_uint(ap[4]);
            unsigned a3 = __float_as_uint(ap[8 * SSTR + 4]);
            #pragma unroll
            for (int j = 0; j < 8; j++) {
                unsigned b0 = __float_as_uint(Vts[(8 * j + g) * SSTR + 8 * s + t]);
                unsigned b1 = __float_as_uint(Vts[(8 * j + g) * SSTR + 8 * s + t + 4]);
                mma8(o[j], a0, a1, a2, a3, b0, b1);
            }
        }
    }

    const int rl0 = 16 * w + g;                   // local rows rl0, rl0+8
    if (nc == 1) {
        float i0 = 1.f / l0, i1 = 1.f / l1;
        float* op = out + ((size_t)b * S_ + qt * BQ + rl0) * D_;
        #pragma unroll
        for (int j = 0; j < 8; j++) {
            int c = 8 * j + 2 * t;
            *(float2*)&op[c]          = make_float2(o[j][0] * i0, o[j][1] * i0);
            *(float2*)&op[8 * D_ + c] = make_float2(o[j][2] * i1, o[j][3] * i1);
        }
    } else {
        const int pi = (b * 32 + qt) * 3 + chunk;
        float* po = g_po + (size_t)pi * 128 * 64;
        #pragma unroll
        for (int j = 0; j < 8; j++) {
            int c = 8 * j + 2 * t;
            *(float2*)&po[rl0 * 64 + c]       = make_float2(o[j][0], o[j][1]);
            *(float2*)&po[(rl0 + 8) * 64 + c] = make_float2(o[j][2], o[j][3]);
        }
        if (t == 0) {
            g_pm[pi * 128 + rl0]     = m0;
            g_pm[pi * 128 + rl0 + 8] = m1;
            g_pl[pi * 128 + rl0]     = l0;
            g_pl[pi * 128 + rl0 + 8] = l1;
        }
    }
}

// ---------------------------------------------------------------------------
// Kernel 3: merge split-K partials for qt >= 12.  grid=(80,8), block=256.
// 4 CTAs per (b,qt); float4 vectorized (proven R8 version, 7.7us).
// ---------------------------------------------------------------------------
__global__ void __launch_bounds__(256) merge_kernel(float* __restrict__ out)
{
    const int qt  = 12 + (blockIdx.x >> 2);
    const int sub = blockIdx.x & 3;
    const int b   = blockIdx.y;
    const int nc  = NCHUNK(qt);
    const int pib = (b * 32 + qt) * 3;

    #pragma unroll
    for (int it = 0; it < 2; it++) {
        const int e4 = sub * 512 + it * 256 + threadIdx.x;   // float4 index in [0,2048)
        const int e  = e4 * 4;
        const int r  = e >> 6, col = e & 63;

        float M = -1e30f;
        #pragma unroll
        for (int c = 0; c < 3; c++)
            if (c < nc) M = fmaxf(M, g_pm[(pib + c) * 128 + r]);
        float L = 0.f;
        float4 O = make_float4(0.f, 0.f, 0.f, 0.f);
        #pragma unroll
        for (int c = 0; c < 3; c++)
            if (c < nc) {
                float wgt = __expf(g_pm[(pib + c) * 128 + r] - M);
                L += g_pl[(pib + c) * 128 + r] * wgt;
                float4 v = *(const float4*)&g_po[(size_t)(pib + c) * 8192 + e];
                O.x += v.x * wgt; O.y += v.y * wgt; O.z += v.z * wgt; O.w += v.w * wgt;
            }
        float inv = 1.f / L;
        O.x *= inv; O.y *= inv; O.z *= inv; O.w *= inv;
        *(float4*)&out[((size_t)b * S_ + qt * BQ + r) * D_ + col] = O;
    }
}

// ---------------------------------------------------------------------------
extern "C" void kernel_launch(void* const* d_in, const int* in_sizes, int n_in,
                              void* d_out, int out_size)
{
    const float* x  = (const float*)d_in[0];
    const float* Wq = (const float*)d_in[1];
    const float* bq = (const float*)d_in[2];
    const float* Wk = (const float*)d_in[3];
    const float* bk = (const float*)d_in[4];
    const float* Wv = (const float*)d_in[5];
    const float* bv = (const float*)d_in[6];
    float* out = (float*)d_out;

    cudaFuncSetAttribute(qkv_kernel,        cudaFuncAttributeMaxDynamicSharedMemorySize, QKV_SMEM);
    cudaFuncSetAttribute(attn_chunk_kernel, cudaFuncAttributeMaxDynamicSharedMemorySize, ASMEM);

    wt_kernel<<<(D_ * H_ + 255) / 256, 256>>>(Wq, Wk, Wv);

    dim3 g1((B_ * S_) / BQ, 3);
    qkv_kernel<<<g1, 256, QKV_SMEM>>>(x, bq, bk, bv);

    attn_chunk_kernel<<<480, 256, ASMEM>>>(out);

    dim3 g3(80, 8);
    merge_kernel<<<g3, 256>>>(out);
}

// round 11
// speedup vs baseline: 2.0241x; 1.6075x over previous
#include <cuda_runtime.h>
#include <cuda_fp16.h>
#include <cstdint>

#define B_  8
#define S_  4096
#define H_  768
#define D_  64
#define BQ  128
#define BK  64
#define HSTR 72   // half-element smem row stride; (72/2) % 32 == 4 -> conflict-free frag LDS

// scratch (q,k,v stored as fp16; weights transposed fp32)
__device__ __half g_q [B_ * S_ * D_];        // [b*S + s][d]
__device__ __half g_k [B_ * S_ * D_];        // [b*S + s][d]
__device__ __half g_vt[B_ * D_ * S_];        // transposed: [b][d][s]
__device__ float  g_wt[3][D_ * H_];          // W^T: [n][k]

// split-K partial buffers: index pi = (b*32+qt)*3 + chunk
__device__ float g_po[8 * 32 * 3 * 128 * 64];   // unnormalized O
__device__ float g_pm[8 * 32 * 3 * 128];        // row max
__device__ float g_pl[8 * 32 * 3 * 128];        // row sum

#define NCHUNK(qt) ((qt) < 12 ? 1 : ((qt) < 24 ? 2 : 3))

__device__ __forceinline__ void mma16(float* c, unsigned a0, unsigned a1, unsigned a2, unsigned a3,
                                      unsigned b0, unsigned b1) {
    asm("mma.sync.aligned.m16n8k16.row.col.f32.f16.f16.f32 "
        "{%0,%1,%2,%3}, {%4,%5,%6,%7}, {%8,%9}, {%0,%1,%2,%3};"
        : "+f"(c[0]), "+f"(c[1]), "+f"(c[2]), "+f"(c[3])
        : "r"(a0), "r"(a1), "r"(a2), "r"(a3), "r"(b0), "r"(b1));
}

// float4 -> 4 halfs packed in uint2
__device__ __forceinline__ uint2 f4h4(float4 v) {
    __half2 lo = __floats2half2_rn(v.x, v.y);
    __half2 hi = __floats2half2_rn(v.z, v.w);
    uint2 r;
    r.x = *(unsigned*)&lo;
    r.y = *(unsigned*)&hi;
    return r;
}

// ---------------------------------------------------------------------------
// Kernel 0: transpose W into g_wt
// ---------------------------------------------------------------------------
__global__ void wt_kernel(const float* __restrict__ Wq,
                          const float* __restrict__ Wk,
                          const float* __restrict__ Wv) {
    int idx = blockIdx.x * blockDim.x + threadIdx.x;
    if (idx >= D_ * H_) return;
    int n = idx / H_, k = idx % H_;
    g_wt[0][idx] = Wq[k * D_ + n];
    g_wt[1][idx] = Wk[k * D_ + n];
    g_wt[2][idx] = Wv[k * D_ + n];
}

// ---------------------------------------------------------------------------
// Kernel 1: QKV projection, fp16 mma m16n8k16.
// grid=(256,3), block=256 (8 warps).  Warp w: rows 16w..16w+15, all 64 cols.
// smem: xs[128][HSTR] + ws[64][HSTR] halfs.
// ---------------------------------------------------------------------------
#define QKV_SMEM ((BQ + 64) * HSTR * (int)sizeof(__half))

__global__ void __launch_bounds__(256, 2) qkv_kernel(
    const float* __restrict__ x,
    const float* __restrict__ bq, const float* __restrict__ bk, const float* __restrict__ bv)
{
    extern __shared__ __half smh[];
    __half* xs = smh;                  // [128][HSTR]
    __half* ws = smh + BQ * HSTR;      // [64][HSTR]

    const int p = blockIdx.y;
    const float* wt   = g_wt[p];
    const float* bias = (p == 0) ? bq : ((p == 1) ? bk : bv);

    const int tid = threadIdx.x;
    const int w = tid >> 5, lane = tid & 31, g = lane >> 2, t = lane & 3;
    const int row0 = blockIdx.x * BQ;

    float acc[8][4] = {};

    for (int k0 = 0; k0 < H_; k0 += 64) {
        __syncthreads();
        #pragma unroll
        for (int i = 0; i < 8; i++) {              // x tile 128x64 -> half
            int e = tid + i * 256;
            int r = e >> 4, c4 = (e & 15) * 4;
            float4 v = *(const float4*)&x[(size_t)(row0 + r) * H_ + k0 + c4];
            *(uint2*)&xs[r * HSTR + c4] = f4h4(v);
        }
        #pragma unroll
        for (int i = 0; i < 4; i++) {              // W^T tile 64x64 -> half
            int e = tid + i * 256;
            int r = e >> 4, c4 = (e & 15) * 4;
            float4 v = *(const float4*)&wt[(size_t)r * H_ + k0 + c4];
            *(uint2*)&ws[r * HSTR + c4] = f4h4(v);
        }
        __syncthreads();

        #pragma unroll
        for (int s = 0; s < 4; s++) {              // k = 16s .. 16s+15
            const int kc = 16 * s + 2 * t;
            unsigned a0 = *(unsigned*)&xs[(16 * w + g) * HSTR + kc];
            unsigned a1 = *(unsigned*)&xs[(16 * w + g + 8) * HSTR + kc];
            unsigned a2 = *(unsigned*)&xs[(16 * w + g) * HSTR + kc + 8];
            unsigned a3 = *(unsigned*)&xs[(16 * w + g + 8) * HSTR + kc + 8];
            #pragma unroll
            for (int j = 0; j < 8; j++) {
                unsigned b0 = *(unsigned*)&ws[(8 * j + g) * HSTR + kc];
                unsigned b1 = *(unsigned*)&ws[(8 * j + g) * HSTR + kc + 8];
                mma16(acc[j], a0, a1, a2, a3, b0, b1);
            }
        }
    }

    const int r_g = row0 + 16 * w + g;
    if (p < 2) {
        __half* out = (p == 0) ? g_q : g_k;
        #pragma unroll
        for (int j = 0; j < 8; j++) {
            int c = 8 * j + 2 * t;
            float b0v = __ldg(&bias[c]), b1v = __ldg(&bias[c + 1]);
            *(__half2*)&out[(size_t)r_g * D_ + c]       = __floats2half2_rn(acc[j][0] + b0v, acc[j][1] + b1v);
            *(__half2*)&out[(size_t)(r_g + 8) * D_ + c] = __floats2half2_rn(acc[j][2] + b0v, acc[j][3] + b1v);
        }
    } else {
        int b = r_g >> 12, s0 = r_g & (S_ - 1);
        __half* out = g_vt + (size_t)b * D_ * S_;
        #pragma unroll
        for (int j = 0; j < 8; j++) {
            int c = 8 * j + 2 * t;
            float b0v = __ldg(&bias[c]), b1v = __ldg(&bias[c + 1]);
            out[(size_t)c * S_ + s0]           = __float2half_rn(acc[j][0] + b0v);
            out[(size_t)(c + 1) * S_ + s0]     = __float2half_rn(acc[j][1] + b1v);
            out[(size_t)c * S_ + s0 + 8]       = __float2half_rn(acc[j][2] + b0v);
            out[(size_t)(c + 1) * S_ + s0 + 8] = __float2half_rn(acc[j][3] + b1v);
        }
    }
}

// ---------------------------------------------------------------------------
// Kernel 2: split-K causal flash attention chunk, fp16 mma.
// 480 CTAs = 60 work items x 8 batches, launched heaviest-first (LPT).
// smem: Qs[128] + Ks[64] + Vts[64] + Ps[128], each [.][HSTR] halfs.
// ---------------------------------------------------------------------------
#define ASMEM ((BQ + BK + BK + BQ) * HSTR * (int)sizeof(__half))

__global__ void __launch_bounds__(256, 2) attn_chunk_kernel(float* __restrict__ out)
{
    extern __shared__ __half smh[];
    __half* Qs  = smh;
    __half* Ks  = Qs  + BQ * HSTR;
    __half* Vts = Ks  + BK * HSTR;
    __half* Ps  = Vts + BK * HSTR;

    // decode work item
    const int b  = blockIdx.x & 7;
    const int w_ = blockIdx.x >> 3;        // 0..59
    int qt, chunk;
    if (w_ < 24)      { qt = 23 - (w_ >> 1);        chunk = w_ & 1; }
    else if (w_ < 48) { int u = w_ - 24; qt = 24 + u / 3; chunk = u % 3; }
    else              { qt = 59 - w_;               chunk = 0; }
    const int nkt = 2 * qt + 2;
    const int nc  = NCHUNK(qt);
    const int base = nkt / nc, rem = nkt % nc;
    const int k0  = chunk * base + (chunk < rem ? chunk : rem);
    const int k1  = k0 + base + (chunk < rem ? 1 : 0);

    const int tid = threadIdx.x;
    const int w = tid >> 5, lane = tid & 31, g = lane >> 2, t = lane & 3;

    const __half* q  = g_q  + (size_t)b * S_ * D_;
    const __half* kp = g_k  + (size_t)b * S_ * D_;
    const __half* vt = g_vt + (size_t)b * D_ * S_;

    #pragma unroll
    for (int i = 0; i < 8; i++) {                 // Q tile 128x64 halfs (pure copy)
        int e = tid + i * 256;
        int r = e >> 4, c4 = (e & 15) * 4;
        *(uint2*)&Qs[r * HSTR + c4] = *(const uint2*)&q[(size_t)(qt * BQ + r) * D_ + c4];
    }

    float o[8][4] = {};
    float m0 = -1e30f, m1 = -1e30f, l0 = 0.f, l1 = 0.f;
    const float scale = 0.125f;                   // 1/sqrt(64)

    for (int kt = k0; kt < k1; kt++) {
        __syncthreads();
        #pragma unroll
        for (int i = 0; i < 4; i++) {             // K tile 64x64 halfs
            int e = tid + i * 256;
            int r = e >> 4, c4 = (e & 15) * 4;
            *(uint2*)&Ks[r * HSTR + c4] = *(const uint2*)&kp[(size_t)(kt * BK + r) * D_ + c4];
        }
        #pragma unroll
        for (int i = 0; i < 4; i++) {             // V^T tile [d][key] halfs
            int e = tid + i * 256;
            int r = e >> 4, c4 = (e & 15) * 4;
            *(uint2*)&Vts[r * HSTR + c4] = *(const uint2*)&vt[(size_t)r * S_ + kt * BK + c4];
        }
        __syncthreads();

        // S = Q K^T  (fp16 operands, fp32 accum)
        float sc[8][4] = {};
        #pragma unroll
        for (int s = 0; s < 4; s++) {
            const int kc = 16 * s + 2 * t;
            unsigned a0 = *(unsigned*)&Qs[(16 * w + g) * HSTR + kc];
            unsigned a1 = *(unsigned*)&Qs[(16 * w + g + 8) * HSTR + kc];
            unsigned a2 = *(unsigned*)&Qs[(16 * w + g) * HSTR + kc + 8];
            unsigned a3 = *(unsigned*)&Qs[(16 * w + g + 8) * HSTR + kc + 8];
            #pragma unroll
            for (int j = 0; j < 8; j++) {
                unsigned b0 = *(unsigned*)&Ks[(8 * j + g) * HSTR + kc];
                unsigned b1 = *(unsigned*)&Ks[(8 * j + g) * HSTR + kc + 8];
                mma16(sc[j], a0, a1, a2, a3, b0, b1);
            }
        }

        #pragma unroll
        for (int j = 0; j < 8; j++) {
            sc[j][0] *= scale; sc[j][1] *= scale; sc[j][2] *= scale; sc[j][3] *= scale;
        }
        if (kt >= nkt - 2) {                      // diagonal masking (global kt)
            const int row_g = qt * BQ + 16 * w + g;
            #pragma unroll
            for (int j = 0; j < 8; j++) {
                int key = kt * BK + 8 * j + 2 * t;
                if (key     > row_g)     sc[j][0] = -1e30f;
                if (key + 1 > row_g)     sc[j][1] = -1e30f;
                if (key     > row_g + 8) sc[j][2] = -1e30f;
                if (key + 1 > row_g + 8) sc[j][3] = -1e30f;
            }
        }

        // online softmax; rows g (regs 0,1) and g+8 (regs 2,3) in-warp
        float mt0 = -1e30f, mt1 = -1e30f;
        #pragma unroll
        for (int j = 0; j < 8; j++) {
            mt0 = fmaxf(mt0, fmaxf(sc[j][0], sc[j][1]));
            mt1 = fmaxf(mt1, fmaxf(sc[j][2], sc[j][3]));
        }
        mt0 = fmaxf(mt0, __shfl_xor_sync(~0u, mt0, 1));
        mt0 = fmaxf(mt0, __shfl_xor_sync(~0u, mt0, 2));
        mt1 = fmaxf(mt1, __shfl_xor_sync(~0u, mt1, 1));
        mt1 = fmaxf(mt1, __shfl_xor_sync(~0u, mt1, 2));
        float mn0 = fmaxf(m0, mt0), mn1 = fmaxf(m1, mt1);
        float c0 = __expf(m0 - mn0), c1 = __expf(m1 - mn1);
        m0 = mn0; m1 = mn1;

        float rs0 = 0.f, rs1 = 0.f;
        __half* prow0 = &Ps[(16 * w + g) * HSTR];
        __half* prow1 = prow0 + 8 * HSTR;
        #pragma unroll
        for (int j = 0; j < 8; j++) {
            float e0 = __expf(sc[j][0] - mn0), e1 = __expf(sc[j][1] - mn0);
            float e2 = __expf(sc[j][2] - mn1), e3 = __expf(sc[j][3] - mn1);
            rs0 += e0 + e1; rs1 += e2 + e3;
            int c = 8 * j + 2 * t;
            *(__half2*)&prow0[c] = __floats2half2_rn(e0, e1);
            *(__half2*)&prow1[c] = __floats2half2_rn(e2, e3);
        }
        rs0 += __shfl_xor_sync(~0u, rs0, 1); rs0 += __shfl_xor_sync(~0u, rs0, 2);
        rs1 += __shfl_xor_sync(~0u, rs1, 1); rs1 += __shfl_xor_sync(~0u, rs1, 2);
        l0 = l0 * c0 + rs0; l1 = l1 * c1 + rs1;
        #pragma unroll
        for (int j = 0; j < 8; j++) {
            o[j][0] *= c0; o[j][1] *= c0; o[j][2] *= c1; o[j][3] *= c1;
        }
        __syncwarp();   // this warp's P rows written before its own frag reads

        // O += P V
        #pragma unroll
        for (int s = 0; s < 4; s++) {
            const int kc = 16 * s + 2 * t;
            unsigned a0 = *(unsigned*)&Ps[(16 * w + g) * HSTR + kc];
            unsigned a1 = *(unsigned*)&Ps[(16 * w + g + 8) * HSTR + kc];
            unsigned a2 = *(unsigned*)&Ps[(16 * w + g) * HSTR + kc + 8];
            unsigned a3 = *(unsigned*)&Ps[(16 * w + g + 8) * HSTR + kc + 8];
            #pragma unroll
            for (int j = 0; j < 8; j++) {
                unsigned b0 = *(unsigned*)&Vts[(8 * j + g) * HSTR + kc];
                unsigned b1 = *(unsigned*)&Vts[(8 * j + g) * HSTR + kc + 8];
                mma16(o[j], a0, a1, a2, a3, b0, b1);
            }
        }
    }

    const int rl0 = 16 * w + g;                   // local rows rl0, rl0+8
    if (nc == 1) {
        float i0 = 1.f / l0, i1 = 1.f / l1;
        float* op = out + ((size_t)b * S_ + qt * BQ + rl0) * D_;
        #pragma unroll
        for (int j = 0; j < 8; j++) {
            int c = 8 * j + 2 * t;
            *(float2*)&op[c]          = make_float2(o[j][0] * i0, o[j][1] * i0);
            *(float2*)&op[8 * D_ + c] = make_float2(o[j][2] * i1, o[j][3] * i1);
        }
    } else {
        const int pi = (b * 32 + qt) * 3 + chunk;
        float* po = g_po + (size_t)pi * 128 * 64;
        #pragma unroll
        for (int j = 0; j < 8; j++) {
            int c = 8 * j + 2 * t;
            *(float2*)&po[rl0 * 64 + c]       = make_float2(o[j][0], o[j][1]);
            *(float2*)&po[(rl0 + 8) * 64 + c] = make_float2(o[j][2], o[j][3]);
        }
        if (t == 0) {
            g_pm[pi * 128 + rl0]     = m0;
            g_pm[pi * 128 + rl0 + 8] = m1;
            g_pl[pi * 128 + rl0]     = l0;
            g_pl[pi * 128 + rl0 + 8] = l1;
        }
    }
}

// ---------------------------------------------------------------------------
// Kernel 3: merge split-K partials for qt >= 12.  grid=(80,8), block=256.
// (proven R10 version, 7.5us)
// ---------------------------------------------------------------------------
__global__ void __launch_bounds__(256) merge_kernel(float* __restrict__ out)
{
    const int qt  = 12 + (blockIdx.x >> 2);
    const int sub = blockIdx.x & 3;
    const int b   = blockIdx.y;
    const int nc  = NCHUNK(qt);
    const int pib = (b * 32 + qt) * 3;

    #pragma unroll
    for (int it = 0; it < 2; it++) {
        const int e4 = sub * 512 + it * 256 + threadIdx.x;   // float4 index in [0,2048)
        const int e  = e4 * 4;
        const int r  = e >> 6, col = e & 63;

        float M = -1e30f;
        #pragma unroll
        for (int c = 0; c < 3; c++)
            if (c < nc) M = fmaxf(M, g_pm[(pib + c) * 128 + r]);
        float L = 0.f;
        float4 O = make_float4(0.f, 0.f, 0.f, 0.f);
        #pragma unroll
        for (int c = 0; c < 3; c++)
            if (c < nc) {
                float wgt = __expf(g_pm[(pib + c) * 128 + r] - M);
                L += g_pl[(pib + c) * 128 + r] * wgt;
                float4 v = *(const float4*)&g_po[(size_t)(pib + c) * 8192 + e];
                O.x += v.x * wgt; O.y += v.y * wgt; O.z += v.z * wgt; O.w += v.w * wgt;
            }
        float inv = 1.f / L;
        O.x *= inv; O.y *= inv; O.z *= inv; O.w *= inv;
        *(float4*)&out[((size_t)b * S_ + qt * BQ + r) * D_ + col] = O;
    }
}

// ---------------------------------------------------------------------------
extern "C" void kernel_launch(void* const* d_in, const int* in_sizes, int n_in,
                              void* d_out, int out_size)
{
    const float* x  = (const float*)d_in[0];
    const float* Wq = (const float*)d_in[1];
    const float* bq = (const float*)d_in[2];
    const float* Wk = (const float*)d_in[3];
    const float* bk = (const float*)d_in[4];
    const float* Wv = (const float*)d_in[5];
    const float* bv = (const float*)d_in[6];
    float* out = (float*)d_out;

    cudaFuncSetAttribute(qkv_kernel,        cudaFuncAttributeMaxDynamicSharedMemorySize, QKV_SMEM);
    cudaFuncSetAttribute(attn_chunk_kernel, cudaFuncAttributeMaxDynamicSharedMemorySize, ASMEM);

    wt_kernel<<<(D_ * H_ + 255) / 256, 256>>>(Wq, Wk, Wv);

    dim3 g1((B_ * S_) / BQ, 3);
    qkv_kernel<<<g1, 256, QKV_SMEM>>>(x, bq, bk, bv);

    attn_chunk_kernel<<<480, 256, ASMEM>>>(out);

    dim3 g3(80, 8);
    merge_kernel<<<g3, 256>>>(out);
}

// round 14
// speedup vs baseline: 2.1322x; 1.0534x over previous
#include <cuda_runtime.h>
#include <cuda_fp16.h>
#include <cstdint>

#define B_  8
#define S_  4096
#define H_  768
#define D_  64
#define BQ  128
#define BK  64
#define HSTR 72   // half-element smem row stride; (72/2) % 32 == 4 -> conflict-free frag LDS

// scratch (q,k,v stored as fp16; weights transposed fp32)
__device__ __half g_q [B_ * S_ * D_];        // [b*S + s][d]
__device__ __half g_k [B_ * S_ * D_];        // [b*S + s][d]
__device__ __half g_vt[B_ * D_ * S_];        // transposed: [b][d][s]
__device__ float  g_wt[3][D_ * H_];          // W^T: [n][k]

// split-K partial buffers: index pi = (b*32+qt)*3 + chunk
__device__ float g_po[8 * 32 * 3 * 128 * 64];   // unnormalized O
__device__ float g_pm[8 * 32 * 3 * 128];        // row max
__device__ float g_pl[8 * 32 * 3 * 128];        // row sum

#define NCHUNK(qt) ((qt) < 12 ? 1 : ((qt) < 24 ? 2 : 3))

__device__ __forceinline__ void mma16(float* c, unsigned a0, unsigned a1, unsigned a2, unsigned a3,
                                      unsigned b0, unsigned b1) {
    asm("mma.sync.aligned.m16n8k16.row.col.f32.f16.f16.f32 "
        "{%0,%1,%2,%3}, {%4,%5,%6,%7}, {%8,%9}, {%0,%1,%2,%3};"
        : "+f"(c[0]), "+f"(c[1]), "+f"(c[2]), "+f"(c[3])
        : "r"(a0), "r"(a1), "r"(a2), "r"(a3), "r"(b0), "r"(b1));
}

// float4 -> 4 halfs packed in uint2
__device__ __forceinline__ uint2 f4h4(float4 v) {
    __half2 lo = __floats2half2_rn(v.x, v.y);
    __half2 hi = __floats2half2_rn(v.z, v.w);
    uint2 r;
    r.x = *(unsigned*)&lo;
    r.y = *(unsigned*)&hi;
    return r;
}
__device__ __forceinline__ unsigned pack2(float a, float b) {
    __half2 h = __floats2half2_rn(a, b);
    return *(unsigned*)&h;
}

// ---------------------------------------------------------------------------
// Kernel 0: transpose W into g_wt
// ---------------------------------------------------------------------------
__global__ void wt_kernel(const float* __restrict__ Wq,
                          const float* __restrict__ Wk,
                          const float* __restrict__ Wv) {
    int idx = blockIdx.x * blockDim.x + threadIdx.x;
    if (idx >= D_ * H_) return;
    int n = idx / H_, k = idx % H_;
    g_wt[0][idx] = Wq[k * D_ + n];
    g_wt[1][idx] = Wk[k * D_ + n];
    g_wt[2][idx] = Wv[k * D_ + n];
}

// ---------------------------------------------------------------------------
// Kernel 1: QKV projection, fp16 mma m16n8k16 (proven R11 version).
// ---------------------------------------------------------------------------
#define QKV_SMEM ((BQ + 64) * HSTR * (int)sizeof(__half))

__global__ void __launch_bounds__(256, 2) qkv_kernel(
    const float* __restrict__ x,
    const float* __restrict__ bq, const float* __restrict__ bk, const float* __restrict__ bv)
{
    extern __shared__ __half smh[];
    __half* xs = smh;                  // [128][HSTR]
    __half* ws = smh + BQ * HSTR;      // [64][HSTR]

    const int p = blockIdx.y;
    const float* wt   = g_wt[p];
    const float* bias = (p == 0) ? bq : ((p == 1) ? bk : bv);

    const int tid = threadIdx.x;
    const int w = tid >> 5, lane = tid & 31, g = lane >> 2, t = lane & 3;
    const int row0 = blockIdx.x * BQ;

    float acc[8][4] = {};

    for (int k0 = 0; k0 < H_; k0 += 64) {
        __syncthreads();
        #pragma unroll
        for (int i = 0; i < 8; i++) {              // x tile 128x64 -> half
            int e = tid + i * 256;
            int r = e >> 4, c4 = (e & 15) * 4;
            float4 v = *(const float4*)&x[(size_t)(row0 + r) * H_ + k0 + c4];
            *(uint2*)&xs[r * HSTR + c4] = f4h4(v);
        }
        #pragma unroll
        for (int i = 0; i < 4; i++) {              // W^T tile 64x64 -> half
            int e = tid + i * 256;
            int r = e >> 4, c4 = (e & 15) * 4;
            float4 v = *(const float4*)&wt[(size_t)r * H_ + k0 + c4];
            *(uint2*)&ws[r * HSTR + c4] = f4h4(v);
        }
        __syncthreads();

        #pragma unroll
        for (int s = 0; s < 4; s++) {              // k = 16s .. 16s+15
            const int kc = 16 * s + 2 * t;
            unsigned a0 = *(unsigned*)&xs[(16 * w + g) * HSTR + kc];
            unsigned a1 = *(unsigned*)&xs[(16 * w + g + 8) * HSTR + kc];
            unsigned a2 = *(unsigned*)&xs[(16 * w + g) * HSTR + kc + 8];
            unsigned a3 = *(unsigned*)&xs[(16 * w + g + 8) * HSTR + kc + 8];
            #pragma unroll
            for (int j = 0; j < 8; j++) {
                unsigned b0 = *(unsigned*)&ws[(8 * j + g) * HSTR + kc];
                unsigned b1 = *(unsigned*)&ws[(8 * j + g) * HSTR + kc + 8];
                mma16(acc[j], a0, a1, a2, a3, b0, b1);
            }
        }
    }

    const int r_g = row0 + 16 * w + g;
    if (p < 2) {
        __half* out = (p == 0) ? g_q : g_k;
        #pragma unroll
        for (int j = 0; j < 8; j++) {
            int c = 8 * j + 2 * t;
            float b0v = __ldg(&bias[c]), b1v = __ldg(&bias[c + 1]);
            *(__half2*)&out[(size_t)r_g * D_ + c]       = __floats2half2_rn(acc[j][0] + b0v, acc[j][1] + b1v);
            *(__half2*)&out[(size_t)(r_g + 8) * D_ + c] = __floats2half2_rn(acc[j][2] + b0v, acc[j][3] + b1v);
        }
    } else {
        int b = r_g >> 12, s0 = r_g & (S_ - 1);
        __half* out = g_vt + (size_t)b * D_ * S_;
        #pragma unroll
        for (int j = 0; j < 8; j++) {
            int c = 8 * j + 2 * t;
            float b0v = __ldg(&bias[c]), b1v = __ldg(&bias[c + 1]);
            out[(size_t)c * S_ + s0]           = __float2half_rn(acc[j][0] + b0v);
            out[(size_t)(c + 1) * S_ + s0]     = __float2half_rn(acc[j][1] + b1v);
            out[(size_t)c * S_ + s0 + 8]       = __float2half_rn(acc[j][2] + b0v);
            out[(size_t)(c + 1) * S_ + s0 + 8] = __float2half_rn(acc[j][3] + b1v);
        }
    }
}

// ---------------------------------------------------------------------------
// Kernel 2: split-K causal flash attention chunk, fp16 mma,
// REGISTER-RESIDENT P: the S C-fragment is re-packed in regs as the PV
// A-fragment (cols 8j+2t <-> k=16s+2t with j=2s / 2s+1).  No P smem.
// smem: Qs[128] + Ks[64] + Vts[64], each [.][HSTR] halfs.
// ---------------------------------------------------------------------------
#define ASMEM ((BQ + BK + BK) * HSTR * (int)sizeof(__half))

__global__ void __launch_bounds__(256, 2) attn_chunk_kernel(float* __restrict__ out)
{
    extern __shared__ __half smh[];
    __half* Qs  = smh;
    __half* Ks  = Qs  + BQ * HSTR;
    __half* Vts = Ks  + BK * HSTR;

    // decode work item
    const int b  = blockIdx.x & 7;
    const int w_ = blockIdx.x >> 3;        // 0..59
    int qt, chunk;
    if (w_ < 24)      { qt = 23 - (w_ >> 1);        chunk = w_ & 1; }
    else if (w_ < 48) { int u = w_ - 24; qt = 24 + u / 3; chunk = u % 3; }
    else              { qt = 59 - w_;               chunk = 0; }
    const int nkt = 2 * qt + 2;
    const int nc  = NCHUNK(qt);
    const int base = nkt / nc, rem = nkt % nc;
    const int k0  = chunk * base + (chunk < rem ? chunk : rem);
    const int k1  = k0 + base + (chunk < rem ? 1 : 0);

    const int tid = threadIdx.x;
    const int w = tid >> 5, lane = tid & 31, g = lane >> 2, t = lane & 3;

    const __half* q  = g_q  + (size_t)b * S_ * D_;
    const __half* kp = g_k  + (size_t)b * S_ * D_;
    const __half* vt = g_vt + (size_t)b * D_ * S_;

    #pragma unroll
    for (int i = 0; i < 8; i++) {                 // Q tile 128x64 halfs (pure copy)
        int e = tid + i * 256;
        int r = e >> 4, c4 = (e & 15) * 4;
        *(uint2*)&Qs[r * HSTR + c4] = *(const uint2*)&q[(size_t)(qt * BQ + r) * D_ + c4];
    }

    float o[8][4] = {};
    float m0 = -1e30f, m1 = -1e30f, l0 = 0.f, l1 = 0.f;
    const float scale = 0.125f;                   // 1/sqrt(64)

    for (int kt = k0; kt < k1; kt++) {
        __syncthreads();
        #pragma unroll
        for (int i = 0; i < 4; i++) {             // K tile 64x64 halfs
            int e = tid + i * 256;
            int r = e >> 4, c4 = (e & 15) * 4;
            *(uint2*)&Ks[r * HSTR + c4] = *(const uint2*)&kp[(size_t)(kt * BK + r) * D_ + c4];
        }
        #pragma unroll
        for (int i = 0; i < 4; i++) {             // V^T tile [d][key] halfs
            int e = tid + i * 256;
            int r = e >> 4, c4 = (e & 15) * 4;
            *(uint2*)&Vts[r * HSTR + c4] = *(const uint2*)&vt[(size_t)r * S_ + kt * BK + c4];
        }
        __syncthreads();

        // S = Q K^T  (fp16 operands, fp32 accum)
        float sc[8][4] = {};
        #pragma unroll
        for (int s = 0; s < 4; s++) {
            const int kc = 16 * s + 2 * t;
            unsigned a0 = *(unsigned*)&Qs[(16 * w + g) * HSTR + kc];
            unsigned a1 = *(unsigned*)&Qs[(16 * w + g + 8) * HSTR + kc];
            unsigned a2 = *(unsigned*)&Qs[(16 * w + g) * HSTR + kc + 8];
            unsigned a3 = *(unsigned*)&Qs[(16 * w + g + 8) * HSTR + kc + 8];
            #pragma unroll
            for (int j = 0; j < 8; j++) {
                unsigned b0 = *(unsigned*)&Ks[(8 * j + g) * HSTR + kc];
                unsigned b1 = *(unsigned*)&Ks[(8 * j + g) * HSTR + kc + 8];
                mma16(sc[j], a0, a1, a2, a3, b0, b1);
            }
        }

        #pragma unroll
        for (int j = 0; j < 8; j++) {
            sc[j][0] *= scale; sc[j][1] *= scale; sc[j][2] *= scale; sc[j][3] *= scale;
        }
        if (kt >= nkt - 2) {                      // diagonal masking (global kt)
            const int row_g = qt * BQ + 16 * w + g;
            #pragma unroll
            for (int j = 0; j < 8; j++) {
                int key = kt * BK + 8 * j + 2 * t;
                if (key     > row_g)     sc[j][0] = -1e30f;
                if (key + 1 > row_g)     sc[j][1] = -1e30f;
                if (key     > row_g + 8) sc[j][2] = -1e30f;
                if (key + 1 > row_g + 8) sc[j][3] = -1e30f;
            }
        }

        // online softmax; rows g (regs 0,1) and g+8 (regs 2,3) in-warp
        float mt0 = -1e30f, mt1 = -1e30f;
        #pragma unroll
        for (int j = 0; j < 8; j++) {
            mt0 = fmaxf(mt0, fmaxf(sc[j][0], sc[j][1]));
            mt1 = fmaxf(mt1, fmaxf(sc[j][2], sc[j][3]));
        }
        mt0 = fmaxf(mt0, __shfl_xor_sync(~0u, mt0, 1));
        mt0 = fmaxf(mt0, __shfl_xor_sync(~0u, mt0, 2));
        mt1 = fmaxf(mt1, __shfl_xor_sync(~0u, mt1, 1));
        mt1 = fmaxf(mt1, __shfl_xor_sync(~0u, mt1, 2));
        float mn0 = fmaxf(m0, mt0), mn1 = fmaxf(m1, mt1);
        float c0 = __expf(m0 - mn0), c1 = __expf(m1 - mn1);
        m0 = mn0; m1 = mn1;

        // exp + pack P directly into PV A-fragments (no smem)
        unsigned pr0[8], pr1[8];                  // pr0: row g; pr1: row g+8 (cols 8j+2t,+1)
        float rs0 = 0.f, rs1 = 0.f;
        #pragma unroll
        for (int j = 0; j < 8; j++) {
            float e0 = __expf(sc[j][0] - mn0), e1 = __expf(sc[j][1] - mn0);
            float e2 = __expf(sc[j][2] - mn1), e3 = __expf(sc[j][3] - mn1);
            rs0 += e0 + e1; rs1 += e2 + e3;
            pr0[j] = pack2(e0, e1);
            pr1[j] = pack2(e2, e3);
        }
        rs0 += __shfl_xor_sync(~0u, rs0, 1); rs0 += __shfl_xor_sync(~0u, rs0, 2);
        rs1 += __shfl_xor_sync(~0u, rs1, 1); rs1 += __shfl_xor_sync(~0u, rs1, 2);
        l0 = l0 * c0 + rs0; l1 = l1 * c1 + rs1;
        #pragma unroll
        for (int j = 0; j < 8; j++) {
            o[j][0] *= c0; o[j][1] *= c0; o[j][2] *= c1; o[j][3] *= c1;
        }

        // O += P V : A-frag from regs (j=2s -> a0/a1, j=2s+1 -> a2/a3)
        #pragma unroll
        for (int s = 0; s < 4; s++) {
            const int kc = 16 * s + 2 * t;
            unsigned a0 = pr0[2 * s];
            unsigned a1 = pr1[2 * s];
            unsigned a2 = pr0[2 * s + 1];
            unsigned a3 = pr1[2 * s + 1];
            #pragma unroll
            for (int j = 0; j < 8; j++) {
                unsigned b0 = *(unsigned*)&Vts[(8 * j + g) * HSTR + kc];
                unsigned b1 = *(unsigned*)&Vts[(8 * j + g) * HSTR + kc + 8];
                mma16(o[j], a0, a1, a2, a3, b0, b1);
            }
        }
    }

    const int rl0 = 16 * w + g;                   // local rows rl0, rl0+8
    if (nc == 1) {
        float i0 = 1.f / l0, i1 = 1.f / l1;
        float* op = out + ((size_t)b * S_ + qt * BQ + rl0) * D_;
        #pragma unroll
        for (int j = 0; j < 8; j++) {
            int c = 8 * j + 2 * t;
            *(float2*)&op[c]          = make_float2(o[j][0] * i0, o[j][1] * i0);
            *(float2*)&op[8 * D_ + c] = make_float2(o[j][2] * i1, o[j][3] * i1);
        }
    } else {
        const int pi = (b * 32 + qt) * 3 + chunk;
        float* po = g_po + (size_t)pi * 128 * 64;
        #pragma unroll
        for (int j = 0; j < 8; j++) {
            int c = 8 * j + 2 * t;
            *(float2*)&po[rl0 * 64 + c]       = make_float2(o[j][0], o[j][1]);
            *(float2*)&po[(rl0 + 8) * 64 + c] = make_float2(o[j][2], o[j][3]);
        }
        if (t == 0) {
            g_pm[pi * 128 + rl0]     = m0;
            g_pm[pi * 128 + rl0 + 8] = m1;
            g_pl[pi * 128 + rl0]     = l0;
            g_pl[pi * 128 + rl0 + 8] = l1;
        }
    }
}

// ---------------------------------------------------------------------------
// Kernel 3: merge split-K partials for qt >= 12.  grid=(80,8), block=256.
// (proven R10 version, 7.5us)
// ---------------------------------------------------------------------------
__global__ void __launch_bounds__(256) merge_kernel(float* __restrict__ out)
{
    const int qt  = 12 + (blockIdx.x >> 2);
    const int sub = blockIdx.x & 3;
    const int b   = blockIdx.y;
    const int nc  = NCHUNK(qt);
    const int pib = (b * 32 + qt) * 3;

    #pragma unroll
    for (int it = 0; it < 2; it++) {
        const int e4 = sub * 512 + it * 256 + threadIdx.x;   // float4 index in [0,2048)
        const int e  = e4 * 4;
        const int r  = e >> 6, col = e & 63;

        float M = -1e30f;
        #pragma unroll
        for (int c = 0; c < 3; c++)
            if (c < nc) M = fmaxf(M, g_pm[(pib + c) * 128 + r]);
        float L = 0.f;
        float4 O = make_float4(0.f, 0.f, 0.f, 0.f);
        #pragma unroll
        for (int c = 0; c < 3; c++)
            if (c < nc) {
                float wgt = __expf(g_pm[(pib + c) * 128 + r] - M);
                L += g_pl[(pib + c) * 128 + r] * wgt;
                float4 v = *(const float4*)&g_po[(size_t)(pib + c) * 8192 + e];
                O.x += v.x * wgt; O.y += v.y * wgt; O.z += v.z * wgt; O.w += v.w * wgt;
            }
        float inv = 1.f / L;
        O.x *= inv; O.y *= inv; O.z *= inv; O.w *= inv;
        *(float4*)&out[((size_t)b * S_ + qt * BQ + r) * D_ + col] = O;
    }
}

// ---------------------------------------------------------------------------
extern "C" void kernel_launch(void* const* d_in, const int* in_sizes, int n_in,
                              void* d_out, int out_size)
{
    const float* x  = (const float*)d_in[0];
    const float* Wq = (const float*)d_in[1];
    const float* bq = (const float*)d_in[2];
    const float* Wk = (const float*)d_in[3];
    const float* bk = (const float*)d_in[4];
    const float* Wv = (const float*)d_in[5];
    const float* bv = (const float*)d_in[6];
    float* out = (float*)d_out;

    cudaFuncSetAttribute(qkv_kernel,        cudaFuncAttributeMaxDynamicSharedMemorySize, QKV_SMEM);
    cudaFuncSetAttribute(attn_chunk_kernel, cudaFuncAttributeMaxDynamicSharedMemorySize, ASMEM);

    wt_kernel<<<(D_ * H_ + 255) / 256, 256>>>(Wq, Wk, Wv);

    dim3 g1((B_ * S_) / BQ, 3);
    qkv_kernel<<<g1, 256, QKV_SMEM>>>(x, bq, bk, bv);

    attn_chunk_kernel<<<480, 256, ASMEM>>>(out);

    dim3 g3(80, 8);
    merge_kernel<<<g3, 256>>>(out);
}